// round 1
// baseline (speedup 1.0000x reference)
#include <cuda_runtime.h>
#include <math.h>

#define NTOK   1024
#define NG     32
#define NROWS  (NTOK * NG)      // 32768
#define EMB    32
#define FDIM   128

// flat output layout (all float32):
//   [0, 1048576)                xe  (32768 x 32)
//   [1048576, 34603008)         src (G*n*n)
//   [34603008, 68157440)        dst (G*n*n)
//   [68157440, 101711872)       edge_weight (G*n*n)
#define XE_ELEMS ((size_t)NROWS * EMB)                 // 1,048,576
#define EDGES    ((size_t)NG * NTOK * NTOK)            // 33,554,432
#define OFF_SRC  (XE_ELEMS)
#define OFF_DST  (OFF_SRC + EDGES)
#define OFF_W    (OFF_DST + EDGES)

// scratch (no allocations allowed)
__device__ float g_xe[NROWS * EMB];   // 4 MB
__device__ float g_xg[NROWS * EMB];   // 4 MB
__device__ float g_sq[NROWS];
__device__ float g_cent[EMB];
__device__ float g_scale;

// ---------------------------------------------------------------------------
// Kernel A: xe = x @ W   (32768x128 @ 128x32), write to out[0..] and g_xe
// block = 256 threads, 32 rows per block, grid = 1024
// ---------------------------------------------------------------------------
__global__ __launch_bounds__(256) void k_gemm(const float* __restrict__ x,
                                              const float* __restrict__ W,
                                              float* __restrict__ out) {
    __shared__ float sX[32][132];   // pad 132: rows land on distinct banks
    __shared__ float sW[128][32];   // 128B rows: float4 reads conflict-free
    const int t = threadIdx.x;
    const int row0 = blockIdx.x * 32;

    // stage x tile (32x128) and full W (128x32): 1024 float4 each
    #pragma unroll
    for (int v = t; v < 1024; v += 256) {
        int r  = v >> 5;
        int kq = (v & 31) << 2;
        *(float4*)&sX[r][kq] = *(const float4*)&x[(size_t)(row0 + r) * FDIM + kq];
        int wk = v >> 3;
        int wc = (v & 7) << 2;
        *(float4*)&sW[wk][wc] = *(const float4*)&W[(size_t)v << 2];
    }
    __syncthreads();

    const int r  = t >> 3;          // 0..31
    const int c4 = (t & 7) << 2;    // 0,4,..,28
    float a0 = 0.f, a1 = 0.f, a2 = 0.f, a3 = 0.f;
    #pragma unroll 8
    for (int k = 0; k < FDIM; k++) {
        float  a = sX[r][k];
        float4 w = *(const float4*)&sW[k][c4];
        a0 = fmaf(a, w.x, a0);
        a1 = fmaf(a, w.y, a1);
        a2 = fmaf(a, w.z, a2);
        a3 = fmaf(a, w.w, a3);
    }
    float4 res = make_float4(a0, a1, a2, a3);
    size_t o = (size_t)(row0 + r) * EMB + c4;
    *(float4*)&out[o]  = res;
    *(float4*)&g_xe[o] = res;
}

// ---------------------------------------------------------------------------
// Kernel B: centroid (column means of first 1024 rows) and scale
// single block of 1024 threads
// ---------------------------------------------------------------------------
__global__ __launch_bounds__(1024) void k_stats() {
    __shared__ float part[32][33];
    __shared__ float cent[EMB];
    __shared__ float redmax[32];
    const int t = threadIdx.x;
    const int c  = t & 31;
    const int rg = t >> 5;          // 32 row groups

    float s = 0.f;
    for (int r = rg; r < NTOK; r += 32)
        s += g_xe[(size_t)r * EMB + c];
    part[rg][c] = s;
    __syncthreads();

    if (t < 32) {
        float sum = 0.f;
        #pragma unroll
        for (int q = 0; q < 32; q++) sum += part[q][t];
        float m = sum * (1.0f / (float)NTOK);
        cent[t]   = m;
        g_cent[t] = m;
    }
    __syncthreads();

    float mx = 0.f;
    for (int idx = t; idx < NTOK * EMB; idx += 1024) {
        float v = fabsf(g_xe[idx] - cent[idx & 31]);
        mx = fmaxf(mx, v);
    }
    #pragma unroll
    for (int o = 16; o; o >>= 1)
        mx = fmaxf(mx, __shfl_xor_sync(0xffffffffu, mx, o));
    if ((t & 31) == 0) redmax[t >> 5] = mx;
    __syncthreads();
    if (t < 32) {
        float mm = redmax[t];
        #pragma unroll
        for (int o = 16; o; o >>= 1)
            mm = fmaxf(mm, __shfl_xor_sync(0xffffffffu, mm, o));
        if (t == 0) g_scale = 0.9f / mm;
    }
}

// ---------------------------------------------------------------------------
// Kernel B2: xg = (xe - centroid) * scale ; sq = ||xg||^2  per row
// one thread per row, grid = 128 x 256
// ---------------------------------------------------------------------------
__global__ __launch_bounds__(256) void k_xg() {
    __shared__ float cent[EMB];
    if (threadIdx.x < EMB) cent[threadIdx.x] = g_cent[threadIdx.x];
    __syncthreads();
    const float scale = g_scale;
    const int row = blockIdx.x * 256 + threadIdx.x;
    float sq = 0.f;
    #pragma unroll
    for (int kq = 0; kq < EMB; kq += 4) {
        float4 v = *(const float4*)&g_xe[(size_t)row * EMB + kq];
        v.x = (v.x - cent[kq + 0]) * scale;
        v.y = (v.y - cent[kq + 1]) * scale;
        v.z = (v.z - cent[kq + 2]) * scale;
        v.w = (v.w - cent[kq + 3]) * scale;
        sq = fmaf(v.x, v.x, sq);
        sq = fmaf(v.y, v.y, sq);
        sq = fmaf(v.z, v.z, sq);
        sq = fmaf(v.w, v.w, sq);
        *(float4*)&g_xg[(size_t)row * EMB + kq] = v;
    }
    g_sq[row] = sq;
}

// ---------------------------------------------------------------------------
// Kernel C: pairwise D -> sigmoid weights + src/dst index fills
// grid (16,16,32): per block a 64x64 (i,j) tile of one graph.
// 256 threads, 4x4 micro-tile per thread.
// ---------------------------------------------------------------------------
__global__ __launch_bounds__(256) void k_pair(float* __restrict__ out,
                                              const float* __restrict__ temp,
                                              const float* __restrict__ thr) {
    __shared__ float sxi[64][36];   // pad 36: LDS.128 phases conflict-free
    __shared__ float sxj[64][36];
    __shared__ float sqi[64];
    __shared__ float sqj[64];

    const int t  = threadIdx.x;
    const int g  = blockIdx.z;
    const int i0 = blockIdx.y << 6;
    const int j0 = blockIdx.x << 6;
    const float* xg = g_xg + (size_t)g * NTOK * EMB;

    // stage tiles: 64 rows x 32 cols = 512 float4 per tile
    #pragma unroll
    for (int v = t; v < 64 * 8; v += 256) {
        int r  = v >> 3;
        int kq = (v & 7) << 2;
        *(float4*)&sxi[r][kq] = *(const float4*)&xg[(size_t)(i0 + r) * EMB + kq];
        *(float4*)&sxj[r][kq] = *(const float4*)&xg[(size_t)(j0 + r) * EMB + kq];
    }
    if (t < 64)        sqi[t]      = g_sq[g * NTOK + i0 + t];
    else if (t < 128)  sqj[t - 64] = g_sq[g * NTOK + j0 + (t - 64)];
    __syncthreads();

    const int tx = t & 15, ty = t >> 4;
    const int ib = ty << 2, jb = tx << 2;

    float acc[4][4];
    #pragma unroll
    for (int r = 0; r < 4; r++)
        #pragma unroll
        for (int c = 0; c < 4; c++) acc[r][c] = 0.f;

    #pragma unroll
    for (int k = 0; k < EMB; k += 4) {
        float4 a[4], b[4];
        #pragma unroll
        for (int r = 0; r < 4; r++) a[r] = *(const float4*)&sxi[ib + r][k];
        #pragma unroll
        for (int c = 0; c < 4; c++) b[c] = *(const float4*)&sxj[jb + c][k];
        #pragma unroll
        for (int r = 0; r < 4; r++)
            #pragma unroll
            for (int c = 0; c < 4; c++) {
                acc[r][c] = fmaf(a[r].x, b[c].x, acc[r][c]);
                acc[r][c] = fmaf(a[r].y, b[c].y, acc[r][c]);
                acc[r][c] = fmaf(a[r].z, b[c].z, acc[r][c]);
                acc[r][c] = fmaf(a[r].w, b[c].w, acc[r][c]);
            }
    }

    const float T  = temp[0];
    const float th = fabsf(thr[0]);
    const int   jg = j0 + jb;
    const float dbase = (float)(g * NTOK + jg);
    const float4 d4 = make_float4(dbase, dbase + 1.f, dbase + 2.f, dbase + 3.f);

    #pragma unroll
    for (int r = 0; r < 4; r++) {
        const int   ig = i0 + ib + r;
        const float si = sqi[ib + r];
        float4 w;
        {
            float D = fmaxf(si + sqj[jb + 0] - 2.f * acc[r][0], 0.f);
            float arg = T * (th - D);
            w.x = __fdividef(1.f, 1.f + __expf(-arg));
        }
        {
            float D = fmaxf(si + sqj[jb + 1] - 2.f * acc[r][1], 0.f);
            float arg = T * (th - D);
            w.y = __fdividef(1.f, 1.f + __expf(-arg));
        }
        {
            float D = fmaxf(si + sqj[jb + 2] - 2.f * acc[r][2], 0.f);
            float arg = T * (th - D);
            w.z = __fdividef(1.f, 1.f + __expf(-arg));
        }
        {
            float D = fmaxf(si + sqj[jb + 3] - 2.f * acc[r][3], 0.f);
            float arg = T * (th - D);
            w.w = __fdividef(1.f, 1.f + __expf(-arg));
        }
        const size_t e = ((size_t)g << 20) + ((size_t)ig << 10) + (size_t)jg;
        *(float4*)&out[OFF_W + e] = w;
        const float sv = (float)(g * NTOK + ig);
        *(float4*)&out[OFF_SRC + e] = make_float4(sv, sv, sv, sv);
        *(float4*)&out[OFF_DST + e] = d4;
    }
}

// ---------------------------------------------------------------------------
extern "C" void kernel_launch(void* const* d_in, const int* in_sizes, int n_in,
                              void* d_out, int out_size) {
    const float* x    = (const float*)d_in[0];
    const float* W    = (const float*)d_in[1];
    const float* temp = (const float*)d_in[2];
    const float* thr  = (const float*)d_in[3];
    float* out = (float*)d_out;

    k_gemm<<<NROWS / 32, 256>>>(x, W, out);
    k_stats<<<1, 1024>>>();
    k_xg<<<NROWS / 256, 256>>>();
    dim3 gridC(NTOK / 64, NTOK / 64, NG);
    k_pair<<<gridC, 256>>>(out, temp, thr);
}

// round 2
// speedup vs baseline: 1.3446x; 1.3446x over previous
#include <cuda_runtime.h>
#include <math.h>

#define NTOK   1024
#define NG     32
#define NROWS  (NTOK * NG)      // 32768
#define EMB    32
#define FDIM   128

// flat output layout (all float32):
//   [0, 1048576)                xe  (32768 x 32)
//   [1048576, 34603008)         src (G*n*n)
//   [34603008, 68157440)        dst (G*n*n)
//   [68157440, 101711872)       edge_weight (G*n*n)
#define XE_ELEMS ((size_t)NROWS * EMB)                 // 1,048,576
#define EDGES    ((size_t)NG * NTOK * NTOK)            // 33,554,432
#define OFF_SRC  (XE_ELEMS)
#define OFF_DST  (OFF_SRC + EDGES)
#define OFF_W    (OFF_DST + EDGES)

// scratch (no allocations allowed)
__device__ float g_xe[NROWS * EMB];   // 4 MB
__device__ float g_sq[NROWS];
__device__ float g_cent[EMB];
__device__ float g_scale;

// ---------------------------------------------------------------------------
// Kernel A: xe = x @ W   (32768x128 @ 128x32), write to out[0..] and g_xe
// ---------------------------------------------------------------------------
__global__ __launch_bounds__(256) void k_gemm(const float* __restrict__ x,
                                              const float* __restrict__ W,
                                              float* __restrict__ out) {
    __shared__ float sX[32][132];   // pad 132: rows land on distinct banks
    __shared__ float sW[128][32];
    const int t = threadIdx.x;
    const int row0 = blockIdx.x * 32;

    #pragma unroll
    for (int v = t; v < 1024; v += 256) {
        int r  = v >> 5;
        int kq = (v & 31) << 2;
        *(float4*)&sX[r][kq] = *(const float4*)&x[(size_t)(row0 + r) * FDIM + kq];
        int wk = v >> 3;
        int wc = (v & 7) << 2;
        *(float4*)&sW[wk][wc] = *(const float4*)&W[(size_t)v << 2];
    }
    __syncthreads();

    const int r  = t >> 3;          // 0..31
    const int c4 = (t & 7) << 2;    // 0,4,..,28
    float a0 = 0.f, a1 = 0.f, a2 = 0.f, a3 = 0.f;
    #pragma unroll 8
    for (int k = 0; k < FDIM; k++) {
        float  a = sX[r][k];
        float4 w = *(const float4*)&sW[k][c4];
        a0 = fmaf(a, w.x, a0);
        a1 = fmaf(a, w.y, a1);
        a2 = fmaf(a, w.z, a2);
        a3 = fmaf(a, w.w, a3);
    }
    float4 res = make_float4(a0, a1, a2, a3);
    size_t o = (size_t)(row0 + r) * EMB + c4;
    *(float4*)&out[o]  = res;
    *(float4*)&g_xe[o] = res;
}

// ---------------------------------------------------------------------------
// Kernel B: centroid (column means of first 1024 rows) and scale
// ---------------------------------------------------------------------------
__global__ __launch_bounds__(1024) void k_stats() {
    __shared__ float part[32][33];
    __shared__ float cent[EMB];
    __shared__ float redmax[32];
    const int t = threadIdx.x;
    const int c  = t & 31;
    const int rg = t >> 5;

    float s = 0.f;
    for (int r = rg; r < NTOK; r += 32)
        s += g_xe[(size_t)r * EMB + c];
    part[rg][c] = s;
    __syncthreads();

    if (t < 32) {
        float sum = 0.f;
        #pragma unroll
        for (int q = 0; q < 32; q++) sum += part[q][t];
        float m = sum * (1.0f / (float)NTOK);
        cent[t]   = m;
        g_cent[t] = m;
    }
    __syncthreads();

    float mx = 0.f;
    for (int idx = t; idx < NTOK * EMB; idx += 1024) {
        float v = fabsf(g_xe[idx] - cent[idx & 31]);
        mx = fmaxf(mx, v);
    }
    #pragma unroll
    for (int o = 16; o; o >>= 1)
        mx = fmaxf(mx, __shfl_xor_sync(0xffffffffu, mx, o));
    if ((t & 31) == 0) redmax[t >> 5] = mx;
    __syncthreads();
    if (t < 32) {
        float mm = redmax[t];
        #pragma unroll
        for (int o = 16; o; o >>= 1)
            mm = fmaxf(mm, __shfl_xor_sync(0xffffffffu, mm, o));
        if (t == 0) g_scale = 0.9f / mm;
    }
}

// ---------------------------------------------------------------------------
// Kernel B2: sq[row] = || (xe[row]-cent)*scale ||^2   (normalization fused
// into k_pair staging; no xg array anymore)
// ---------------------------------------------------------------------------
__global__ __launch_bounds__(256) void k_sq() {
    __shared__ float cent[EMB];
    if (threadIdx.x < EMB) cent[threadIdx.x] = g_cent[threadIdx.x];
    __syncthreads();
    const float scale = g_scale;
    const int row = blockIdx.x * 256 + threadIdx.x;
    float sq = 0.f;
    #pragma unroll
    for (int kq = 0; kq < EMB; kq += 4) {
        float4 v = *(const float4*)&g_xe[(size_t)row * EMB + kq];
        v.x = (v.x - cent[kq + 0]) * scale;
        v.y = (v.y - cent[kq + 1]) * scale;
        v.z = (v.z - cent[kq + 2]) * scale;
        v.w = (v.w - cent[kq + 3]) * scale;
        sq = fmaf(v.x, v.x, sq);
        sq = fmaf(v.y, v.y, sq);
        sq = fmaf(v.z, v.z, sq);
        sq = fmaf(v.w, v.w, sq);
    }
    g_sq[row] = sq;
}

// ---------------------------------------------------------------------------
// Kernel C: pairwise D -> sigmoid weights + src/dst index fills
// grid (16,16,32): 64x64 (i,j) tile of one graph. 256 threads, 4x4 micro.
// Smem tiles are K-MAJOR (s[k][row]) so mainloop LDS is conflict-free:
//   b-load: 16 consecutive float4 (2 clean phases), a-load: 2-addr broadcast.
// Normalization (xe-cent)*scale applied during staging.
// ---------------------------------------------------------------------------
__global__ __launch_bounds__(256) void k_pair(float* __restrict__ out,
                                              const float* __restrict__ temp,
                                              const float* __restrict__ thr) {
    __shared__ float sxi[EMB][64];
    __shared__ float sxj[EMB][64];
    __shared__ float sqi[64];
    __shared__ float sqj[64];
    __shared__ float cent[EMB];

    const int t  = threadIdx.x;
    const int g  = blockIdx.z;
    const int i0 = blockIdx.y << 6;
    const int j0 = blockIdx.x << 6;
    const float* xe = g_xe + (size_t)g * NTOK * EMB;

    if (t < EMB) cent[t] = g_cent[t];
    if (t < 64)        sqi[t]      = g_sq[g * NTOK + i0 + t];
    else if (t < 128)  sqj[t - 64] = g_sq[g * NTOK + j0 + (t - 64)];
    __syncthreads();
    const float scale = g_scale;

    // stage + normalize + transpose: v -> row r = v&63, k-quad kq = (v>>6)*4
    // STS banks = r mod 32 (lanes consecutive) -> conflict-free
    #pragma unroll
    for (int v = t; v < 512; v += 256) {
        const int r  = v & 63;
        const int kq = (v >> 6) << 2;
        float4 ci = *(const float4*)&cent[kq];
        float4 a = *(const float4*)&xe[(size_t)(i0 + r) * EMB + kq];
        sxi[kq + 0][r] = (a.x - ci.x) * scale;
        sxi[kq + 1][r] = (a.y - ci.y) * scale;
        sxi[kq + 2][r] = (a.z - ci.z) * scale;
        sxi[kq + 3][r] = (a.w - ci.w) * scale;
        float4 b = *(const float4*)&xe[(size_t)(j0 + r) * EMB + kq];
        sxj[kq + 0][r] = (b.x - ci.x) * scale;
        sxj[kq + 1][r] = (b.y - ci.y) * scale;
        sxj[kq + 2][r] = (b.z - ci.z) * scale;
        sxj[kq + 3][r] = (b.w - ci.w) * scale;
    }
    __syncthreads();

    const int tx = t & 15, ty = t >> 4;
    const int ib = ty << 2, jb = tx << 2;

    float acc[4][4];
    #pragma unroll
    for (int r = 0; r < 4; r++)
        #pragma unroll
        for (int c = 0; c < 4; c++) acc[r][c] = 0.f;

    #pragma unroll 8
    for (int k = 0; k < EMB; k++) {
        float4 a = *(const float4*)&sxi[k][ib];
        float4 b = *(const float4*)&sxj[k][jb];
        acc[0][0] = fmaf(a.x, b.x, acc[0][0]);
        acc[0][1] = fmaf(a.x, b.y, acc[0][1]);
        acc[0][2] = fmaf(a.x, b.z, acc[0][2]);
        acc[0][3] = fmaf(a.x, b.w, acc[0][3]);
        acc[1][0] = fmaf(a.y, b.x, acc[1][0]);
        acc[1][1] = fmaf(a.y, b.y, acc[1][1]);
        acc[1][2] = fmaf(a.y, b.z, acc[1][2]);
        acc[1][3] = fmaf(a.y, b.w, acc[1][3]);
        acc[2][0] = fmaf(a.z, b.x, acc[2][0]);
        acc[2][1] = fmaf(a.z, b.y, acc[2][1]);
        acc[2][2] = fmaf(a.z, b.z, acc[2][2]);
        acc[2][3] = fmaf(a.z, b.w, acc[2][3]);
        acc[3][0] = fmaf(a.w, b.x, acc[3][0]);
        acc[3][1] = fmaf(a.w, b.y, acc[3][1]);
        acc[3][2] = fmaf(a.w, b.z, acc[3][2]);
        acc[3][3] = fmaf(a.w, b.w, acc[3][3]);
    }

    const float T  = temp[0];
    const float th = fabsf(thr[0]);
    const int   jg = j0 + jb;
    const float dbase = (float)(g * NTOK + jg);
    const float4 d4 = make_float4(dbase, dbase + 1.f, dbase + 2.f, dbase + 3.f);

    #pragma unroll
    for (int r = 0; r < 4; r++) {
        const int   ig = i0 + ib + r;
        const float si = sqi[ib + r];
        float4 w;
        {
            float D = fmaxf(si + sqj[jb + 0] - 2.f * acc[r][0], 0.f);
            w.x = __fdividef(1.f, 1.f + __expf(-(T * (th - D))));
        }
        {
            float D = fmaxf(si + sqj[jb + 1] - 2.f * acc[r][1], 0.f);
            w.y = __fdividef(1.f, 1.f + __expf(-(T * (th - D))));
        }
        {
            float D = fmaxf(si + sqj[jb + 2] - 2.f * acc[r][2], 0.f);
            w.z = __fdividef(1.f, 1.f + __expf(-(T * (th - D))));
        }
        {
            float D = fmaxf(si + sqj[jb + 3] - 2.f * acc[r][3], 0.f);
            w.w = __fdividef(1.f, 1.f + __expf(-(T * (th - D))));
        }
        const size_t e = ((size_t)g << 20) + ((size_t)ig << 10) + (size_t)jg;
        const float sv = (float)(g * NTOK + ig);
        __stcs((float4*)&out[OFF_W + e],   w);
        __stcs((float4*)&out[OFF_SRC + e], make_float4(sv, sv, sv, sv));
        __stcs((float4*)&out[OFF_DST + e], d4);
    }
}

// ---------------------------------------------------------------------------
extern "C" void kernel_launch(void* const* d_in, const int* in_sizes, int n_in,
                              void* d_out, int out_size) {
    const float* x    = (const float*)d_in[0];
    const float* W    = (const float*)d_in[1];
    const float* temp = (const float*)d_in[2];
    const float* thr  = (const float*)d_in[3];
    float* out = (float*)d_out;

    k_gemm<<<NROWS / 32, 256>>>(x, W, out);
    k_stats<<<1, 1024>>>();
    k_sq<<<NROWS / 256, 256>>>();
    dim3 gridC(NTOK / 64, NTOK / 64, NG);
    k_pair<<<gridC, 256>>>(out, temp, thr);
}